// round 3
// baseline (speedup 1.0000x reference)
#include <cuda_runtime.h>

// Problem constants (B, N, M, d) = (32, 4096, 4096, 3)
#define BB 32
#define NN 4096
#define MM 4096
#define NCHUNK 8            // n-chunks per batch
#define MHALF  2            // m split per batch
#define NPB (NN / NCHUNK)   // 512 preds per CTA
#define TPB 128             // threads per CTA
#define PPT (NPB / TPB)     // 4 preds per thread
#define MSEG (MM / MHALF)   // 2048 targets per CTA tile

#define RBLK 256            // reduce-1 blocks

// Scratch (no allocations allowed in kernel_launch)
__device__ float4 g_tgt4[BB * MM];            // {x, y, z, 0.5*(x^2+y^2+z^2)}
__device__ float  g_pmin[BB * NN * MHALF];    // partial mins per (b,n,mhalf)
__device__ float  g_bsum[RBLK];               // block partial sums

// ---------------------------------------------------------------------------
// Pack targets into float4 with precomputed half-squared-norm in .w
// ---------------------------------------------------------------------------
__global__ void pack_targets_kernel(const float* __restrict__ tgt) {
    int i = blockIdx.x * blockDim.x + threadIdx.x;
    if (i < BB * MM) {
        float x = tgt[3 * i + 0];
        float y = tgt[3 * i + 1];
        float z = tgt[3 * i + 2];
        float w = 0.5f * (x * x + y * y + z * z);
        g_tgt4[i] = make_float4(x, y, z, w);
    }
}

// ---------------------------------------------------------------------------
// Main kernel: for each pred point, min over a 2048-target tile of
//   r = t2/2 - p.t   (then d2 = p2 + 2*min r in the epilogue)
// Inner loop: 1 broadcast LDS.128 + (3 FFMA + 1 FMNMX) x 4 preds per thread.
// ---------------------------------------------------------------------------
__global__ __launch_bounds__(TPB) void chamfer_min_kernel(const float* __restrict__ pred) {
    __shared__ float4 sT[MSEG];   // 32 KB

    int bx     = blockIdx.x;
    int b      = bx >> 4;         // 16 = NCHUNK * MHALF
    int rem    = bx & 15;
    int nchunk = rem >> 1;
    int mh     = rem & 1;

    // Load this CTA's target tile into shared memory (float4, coalesced)
    const float4* tb = g_tgt4 + b * MM + mh * MSEG;
    #pragma unroll
    for (int i = threadIdx.x; i < MSEG; i += TPB) {
        sT[i] = tb[i];
    }
    __syncthreads();

    // Load and negate this thread's pred points
    float npx[PPT], npy[PPT], npz[PPT], m[PPT];
    int n0 = nchunk * NPB + threadIdx.x;
    #pragma unroll
    for (int j = 0; j < PPT; j++) {
        int n = n0 + j * TPB;
        const float* p = pred + (size_t)(b * NN + n) * 3;
        npx[j] = -p[0];
        npy[j] = -p[1];
        npz[j] = -p[2];
        m[j]   = 3.4028235e38f;
    }

    // Main loop: fma-pipe bound, broadcast shared reads
    #pragma unroll 4
    for (int i = 0; i < MSEG; i++) {
        float4 t = sT[i];
        #pragma unroll
        for (int j = 0; j < PPT; j++) {
            float r = __fmaf_rn(npz[j], t.z, t.w);
            r       = __fmaf_rn(npy[j], t.y, r);
            r       = __fmaf_rn(npx[j], t.x, r);
            m[j]    = fminf(m[j], r);
        }
    }

    #pragma unroll
    for (int j = 0; j < PPT; j++) {
        int n = n0 + j * TPB;
        g_pmin[(size_t)(b * NN + n) * MHALF + mh] = m[j];
    }
}

// ---------------------------------------------------------------------------
// Reduction stage 1: combine m-halves, finish d = sqrt(max(p2 + 2m, 0)),
// tree-sum per block (deterministic).
// ---------------------------------------------------------------------------
__global__ __launch_bounds__(256) void reduce1_kernel(const float* __restrict__ pred) {
    __shared__ float ssum[256];
    int tid = threadIdx.x;
    const int per_block = (BB * NN) / RBLK;  // 512
    float acc = 0.0f;
    #pragma unroll
    for (int k = 0; k < per_block / 256; k++) {
        int i = blockIdx.x * per_block + k * 256 + tid;
        const float* p = pred + (size_t)i * 3;
        float x = p[0], y = p[1], z = p[2];
        float p2 = x * x + y * y + z * z;
        float mm = fminf(g_pmin[2 * i], g_pmin[2 * i + 1]);
        float d2 = fmaxf(__fmaf_rn(2.0f, mm, p2), 0.0f);
        acc += sqrtf(d2);
    }
    ssum[tid] = acc;
    __syncthreads();
    #pragma unroll
    for (int s = 128; s > 0; s >>= 1) {
        if (tid < s) ssum[tid] += ssum[tid + s];
        __syncthreads();
    }
    if (tid == 0) g_bsum[blockIdx.x] = ssum[0];
}

// ---------------------------------------------------------------------------
// Reduction stage 2: sum block partials, divide by B*N (deterministic)
// ---------------------------------------------------------------------------
__global__ __launch_bounds__(RBLK) void reduce2_kernel(float* __restrict__ out) {
    __shared__ float ssum[RBLK];
    int tid = threadIdx.x;
    ssum[tid] = g_bsum[tid];
    __syncthreads();
    #pragma unroll
    for (int s = RBLK / 2; s > 0; s >>= 1) {
        if (tid < s) ssum[tid] += ssum[tid + s];
        __syncthreads();
    }
    if (tid == 0) out[0] = ssum[0] * (1.0f / (float)(BB * NN));
}

// ---------------------------------------------------------------------------
extern "C" void kernel_launch(void* const* d_in, const int* in_sizes, int n_in,
                              void* d_out, int out_size) {
    const float* pred   = (const float*)d_in[0];   // [B, N, 3] f32
    const float* target = (const float*)d_in[1];   // [B, M, 3] f32
    float* out = (float*)d_out;

    pack_targets_kernel<<<(BB * MM + 255) / 256, 256>>>(target);
    chamfer_min_kernel<<<BB * NCHUNK * MHALF, TPB>>>(pred);
    reduce1_kernel<<<RBLK, 256>>>(pred);
    reduce2_kernel<<<1, RBLK>>>(out);
}